// round 1
// baseline (speedup 1.0000x reference)
#include <cuda_runtime.h>
#include <math.h>

#define B 64
#define T 128
#define M 4
#define D 512
#define H 512
#define LNUM 2
#define K 6
#define F5H 2560   // 5*H

// ---------------- persistent scratch (static device arrays; no allocation) ----
__device__ float g_bufA[(size_t)T * B * 2 * D];   // layer0 seq (group-sep) -> layer1 hid
__device__ float g_bufB[(size_t)T * B * 2 * D];   // layer0 hid -> layer1 seq
__device__ float g_shareA[(size_t)T * B * H];     // share_feat0 -> layer1 share out
__device__ float g_shareB[(size_t)T * B * H];     // layer0 share out (layer1 shf input)
__device__ float g_Arow[(size_t)B * 2 * 8 * 512]; // masked concat input, 4096 per (b,j)
__device__ float g_partial[(size_t)4 * B * 2 * F5H];
__device__ float g_cell[(size_t)B * 2 * H];
__device__ float g_shst[(size_t)B * H];
__device__ float g_cum[(size_t)B * H];
__device__ int   g_sel[B * 2 * 2];

// ---------------- share_feat = relu(feat_flat @ l2s_W + b) -------------------
// [8192,2048]@[2048,512]; writes g_shareA[(t*B+b)*H + h]
__global__ __launch_bounds__(256) void k_share(const float* __restrict__ feat,
                                               const float* __restrict__ W,
                                               const float* __restrict__ bias) {
    __shared__ float As[16][64];
    __shared__ float Bs[16][64];
    int tid  = threadIdx.x;
    int row0 = blockIdx.x * 64;
    int col0 = blockIdx.y * 64;
    int tr = tid >> 4, tc = tid & 15;
    float acc[4][4];
#pragma unroll
    for (int i = 0; i < 4; i++)
#pragma unroll
        for (int jj = 0; jj < 4; jj++) acc[i][jj] = 0.f;

    for (int k0 = 0; k0 < M * D; k0 += 16) {
#pragma unroll
        for (int i = 0; i < 4; i++) {
            int idx = tid + i * 256;
            int r = idx >> 4, k = idx & 15;
            As[k][r] = feat[(size_t)(row0 + r) * (M * D) + k0 + k];
        }
#pragma unroll
        for (int i = 0; i < 4; i++) {
            int idx = tid + i * 256;
            int k = idx >> 6, c = idx & 63;
            Bs[k][c] = W[(size_t)(k0 + k) * H + col0 + c];
        }
        __syncthreads();
#pragma unroll
        for (int k = 0; k < 16; k++) {
            float4 a4 = *(const float4*)&As[k][tr * 4];
            float4 b4 = *(const float4*)&Bs[k][tc * 4];
            float av[4] = {a4.x, a4.y, a4.z, a4.w};
            float bv[4] = {b4.x, b4.y, b4.z, b4.w};
#pragma unroll
            for (int i = 0; i < 4; i++)
#pragma unroll
                for (int jj = 0; jj < 4; jj++) acc[i][jj] += av[i] * bv[jj];
        }
        __syncthreads();
    }
#pragma unroll
    for (int i = 0; i < 4; i++) {
        int row = row0 + tr * 4 + i;
        int bb = row >> 7, tt = row & 127;  // row = b*T + t
#pragma unroll
        for (int jj = 0; jj < 4; jj++) {
            int col = col0 + tc * 4 + jj;
            float v = acc[i][jj] + bias[col];
            g_shareA[((size_t)tt * B + bb) * H + col] = v > 0.f ? v : 0.f;
        }
    }
}

// ---------------- group separation -> g_bufA [t][b][j][d] --------------------
__global__ __launch_bounds__(128) void k_groupsep(const float* __restrict__ feat,
                                                  const float* __restrict__ sepW,
                                                  const float* __restrict__ sepb) {
    int bt = blockIdx.x;          // b*T + t
    int b = bt >> 7, t = bt & 127;
    const float* fb = feat + (size_t)bt * (M * D);
    __shared__ float s_lg[M];
    int tid = threadIdx.x;
    int w = tid >> 5, lane = tid & 31;
    if (w < M) {
        float s = 0.f;
        for (int d = lane; d < D; d += 32) s += fb[w * D + d] * sepW[d];
#pragma unroll
        for (int o = 16; o; o >>= 1) s += __shfl_down_sync(0xffffffffu, s, o);
        if (lane == 0) s_lg[w] = s + sepb[0];
    }
    __syncthreads();
    float lg[M], mx = -1e30f;
#pragma unroll
    for (int m = 0; m < M; m++) { lg[m] = s_lg[m]; mx = fmaxf(mx, lg[m]); }
    float e[M], sum = 0.f;
#pragma unroll
    for (int m = 0; m < M; m++) { e[m] = expf(lg[m] - mx); sum += e[m]; }
    float sw[M], cnt0 = 0.f;
#pragma unroll
    for (int m = 0; m < M; m++) { sw[m] = (e[m] > 0.25f * sum) ? 1.f : 0.f; cnt0 += sw[m]; }
    float cnt1 = (float)M - cnt0;
    float inv0 = 1.f / (cnt0 + 1e-8f), inv1 = 1.f / (cnt1 + 1e-8f);
    float* o0 = g_bufA + ((size_t)t * B + b) * 2 * D;
    float* o1 = o0 + D;
    for (int d = tid; d < D; d += 128) {
        float s0 = 0.f, s1 = 0.f;
#pragma unroll
        for (int m = 0; m < M; m++) {
            float v = fb[m * D + d];
            s0 += sw[m] * v;
            s1 += (1.f - sw[m]) * v;
        }
        o0[d] = s0 * inv0;
        o1[d] = s1 * inv1;
    }
}

// ---------------- per-layer state reset --------------------------------------
__global__ void k_zero() {
    int i = blockIdx.x * blockDim.x + threadIdx.x;
    if (i < B * 2 * H) g_cell[i] = 0.f;
    if (i < B * H) { g_shst[i] = 0.f; g_cum[i] = 0.f; }
}

// ---------------- per-step: logits, top-2, build masked concat A row ---------
__global__ __launch_bounds__(256) void k_prep(const float* __restrict__ ctx,
                                              const float* __restrict__ archW,
                                              const float* __restrict__ archb,
                                              int l, int t) {
    const float* seq = l ? g_bufB : g_bufA;
    const float* hid = l ? g_bufA : g_bufB;
    int b = blockIdx.x >> 1, j = blockIdx.x & 1;
    int tid = threadIdx.x;
    __shared__ float s_h1[D];
    __shared__ float s_lg[K];
    __shared__ int s_sel[2];

    if (t >= 1) {
        const float* h1 = hid + ((size_t)(t - 1) * B + b) * 2 * D + (size_t)j * D;
        for (int d = tid; d < D; d += 256) s_h1[d] = h1[d];
    } else {
        for (int d = tid; d < D; d += 256) s_h1[d] = 0.f;
    }
    __syncthreads();

    int w = tid >> 5, lane = tid & 31;
    const float* aW = archW + (size_t)l * H * K;
    if (w < K) {
        float s = 0.f;
        for (int d = lane; d < D; d += 32) s += s_h1[d] * aW[(size_t)d * K + w];
#pragma unroll
        for (int o = 16; o; o >>= 1) s += __shfl_down_sync(0xffffffffu, s, o);
        if (lane == 0) s_lg[w] = s + archb[l * K + w];
    }
    __syncthreads();
    if (tid == 0) {
        int k0 = 0; float best = s_lg[0];
        for (int k = 1; k < K; k++) if (s_lg[k] > best) { best = s_lg[k]; k0 = k; }
        int k1 = -1; float b2 = 0.f;
        for (int k = 0; k < K; k++) {
            if (k == k0) continue;
            if (k1 < 0 || s_lg[k] > b2) { b2 = s_lg[k]; k1 = k; }
        }
        s_sel[0] = k0; s_sel[1] = k1;
        g_sel[(b * 2 + j) * 2] = k0;
        g_sel[(b * 2 + j) * 2 + 1] = k1;
    }
    __syncthreads();
    int k0 = s_sel[0], k1 = s_sel[1];

    float* A = g_Arow + (size_t)(b * 2 + j) * 4096;
    const float* seq_t   = seq + ((size_t)t * B + b) * 2 * D;
    const float* seq_n   = (t + 1 < T) ? seq + ((size_t)(t + 1) * B + b) * 2 * D : 0;
    const float* h_prev  = (t >= 1) ? hid + ((size_t)(t - 1) * B + b) * 2 * D : 0;
    const float* h_prev2 = (t >= 2) ? hid + ((size_t)(t - 2) * B + b) * 2 * D : 0;
    const float* sc = ctx + ((size_t)b * T + t) * H;

    for (int d = tid; d < D; d += 256) {
        A[d]       = seq_t[j * D + d];
        A[512 + d] = s_h1[d];
        float cv[6];
        cv[0] = h_prev2 ? h_prev2[j * D + d] : 0.f;          // h_{t-2}, same group
        cv[1] = seq_n ? seq_n[j * D + d] : 0.f;              // x_{t+1}, same group
        cv[2] = h_prev ? h_prev[(1 - j) * D + d] : 0.f;      // h_{t-1}, other group
        cv[3] = seq_t[(1 - j) * D + d];                      // x_t, other group
        cv[4] = seq_n ? seq_n[(1 - j) * D + d] : 0.f;        // x_{t+1}, other group
        cv[5] = sc[d];                                       // scene
#pragma unroll
        for (int k = 0; k < 6; k++)
            A[(2 + k) * 512 + d] = (k == k0 || k == k1) ? 0.5f * cv[k] : 0.f;
    }
}

// ---------------- per-step GEMM: partial[ks] = A[:,ksK:+1024] @ Wbig ---------
__global__ __launch_bounds__(256) void k_gemm(const float* __restrict__ Wx,
                                              const float* __restrict__ Wh,
                                              const float* __restrict__ Wc,
                                              int l) {
    int j = blockIdx.y, ks = blockIdx.z;
    int col0 = blockIdx.x * 64;
    int tid = threadIdx.x;
    // chunk c: 0->Wx[l][j], 1->Wh[l][j], c>=2 -> Wc[l][j][c-2]
    const float* cp[2];
#pragma unroll
    for (int i = 0; i < 2; i++) {
        int c = ks * 2 + i;
        if (c == 0)      cp[i] = Wx + (size_t)(l * 2 + j) * D * F5H;
        else if (c == 1) cp[i] = Wh + (size_t)(l * 2 + j) * D * F5H;
        else             cp[i] = Wc + ((size_t)(l * 2 + j) * K + (c - 2)) * (size_t)D * F5H;
    }
    __shared__ float As[16][64];
    __shared__ float Bs[16][64];
    int tr = tid >> 4, tc = tid & 15;
    float acc[4][4];
#pragma unroll
    for (int i = 0; i < 4; i++)
#pragma unroll
        for (int jj = 0; jj < 4; jj++) acc[i][jj] = 0.f;

    int kbase = ks * 1024;
    for (int kk = 0; kk < 1024; kk += 16) {
        const float* wb = cp[kk >> 9];
        int krow = kk & 511;
#pragma unroll
        for (int i = 0; i < 4; i++) {
            int idx = tid + i * 256;
            int r = idx >> 4, k = idx & 15;
            As[k][r] = g_Arow[((size_t)r * 2 + j) * 4096 + kbase + kk + k];
        }
#pragma unroll
        for (int i = 0; i < 4; i++) {
            int idx = tid + i * 256;
            int k = idx >> 6, c = idx & 63;
            Bs[k][c] = wb[(size_t)(krow + k) * F5H + col0 + c];
        }
        __syncthreads();
#pragma unroll
        for (int k = 0; k < 16; k++) {
            float4 a4 = *(const float4*)&As[k][tr * 4];
            float4 b4 = *(const float4*)&Bs[k][tc * 4];
            float av[4] = {a4.x, a4.y, a4.z, a4.w};
            float bv[4] = {b4.x, b4.y, b4.z, b4.w};
#pragma unroll
            for (int i = 0; i < 4; i++)
#pragma unroll
                for (int jj = 0; jj < 4; jj++) acc[i][jj] += av[i] * bv[jj];
        }
        __syncthreads();
    }
    float* out = g_partial + (size_t)ks * B * 2 * F5H;
#pragma unroll
    for (int i = 0; i < 4; i++)
#pragma unroll
        for (int jj = 0; jj < 4; jj++)
            out[((size_t)(tr * 4 + i) * 2 + j) * F5H + col0 + tc * 4 + jj] = acc[i][jj];
}

// ---------------- per-step elementwise: cell/h/share update ------------------
__global__ __launch_bounds__(128) void k_finalize(const float* __restrict__ bx,
                                                  const float* __restrict__ bhb,
                                                  const float* __restrict__ bcb,
                                                  int l, int t) {
    float* hid = l ? g_bufA : g_bufB;
    const float* shin = l ? g_shareB : g_shareA;
    float* shout = l ? g_shareA : g_shareB;
    int b = blockIdx.x >> 2;
    int p = (blockIdx.x & 3) * 128 + threadIdx.x;  // 0..511
    float sgsum = 0.f;
#pragma unroll
    for (int j = 0; j < 2; j++) {
        int k0 = g_sel[(b * 2 + j) * 2], k1 = g_sel[(b * 2 + j) * 2 + 1];
        float tot[5];
#pragma unroll
        for (int c = 0; c < 5; c++) {
            int f = c * 512 + p;
            size_t off = ((size_t)b * 2 + j) * F5H + f;
            float v = g_partial[off]
                    + g_partial[(size_t)1 * B * 2 * F5H + off]
                    + g_partial[(size_t)2 * B * 2 * F5H + off]
                    + g_partial[(size_t)3 * B * 2 * F5H + off];
            v += bx[(size_t)(l * 2 + j) * F5H + f] + bhb[(size_t)(l * 2 + j) * F5H + f];
            v += 0.5f * (bcb[((size_t)(l * 2 + j) * K + k0) * F5H + f]
                       + bcb[((size_t)(l * 2 + j) * K + k1) * F5H + f]);
            tot[c] = v;
        }
        float ig = tot[0], fg = tot[1], og = tot[2], sg = tot[3], cc = tot[4];
        size_t ci = ((size_t)b * 2 + j) * H + p;
        float cell = g_cell[ci];
        float sf = 1.f / (1.f + expf(-fg));
        float si = 1.f / (1.f + expf(-ig));
        cell = (1.f - sf) * cell + si * tanhf(cc);
        g_cell[ci] = cell;
        float hv = (1.f / (1.f + expf(-og))) * tanhf(cell);
        hid[((size_t)t * B + b) * 2 * H + (size_t)j * H + p] = hv;
        sgsum += sg;
    }
    float gate = 1.f / (1.f + expf(-sgsum));
    size_t siX = (size_t)b * H + p;
    float shf = shin[((size_t)t * B + b) * H + p];
    float st = g_shst[siX] + gate * shf;
    float cum = g_cum[siX] + gate;
    g_shst[siX] = st;
    g_cum[siX] = cum;
    shout[((size_t)t * B + b) * H + p] = st / cum;
}

// ---------------- output assembly -------------------------------------------
__global__ void k_output(float* __restrict__ out) {
    size_t i = (size_t)blockIdx.x * 256 + threadIdx.x;
    size_t total = (size_t)B * T * 1536;
    if (i >= total) return;
    int c = (int)(i % 1536);
    size_t bt = i / 1536;           // b*T + t
    int b = (int)(bt >> 7), t = (int)(bt & 127);
    float v;
    if (c < 1024) {
        size_t idx = ((size_t)t * B + b) * 1024 + c;  // [t][b][j*512+p]
        v = 0.5f * (g_bufB[idx] + g_bufA[idx]);
    } else {
        int p = c - 1024;
        size_t idx = ((size_t)t * B + b) * H + p;
        v = 0.5f * (g_shareB[idx] + g_shareA[idx]);
    }
    out[i] = v;
}

// ---------------- launch ------------------------------------------------------
extern "C" void kernel_launch(void* const* d_in, const int* in_sizes, int n_in,
                              void* d_out, int out_size) {
    const float* feat = (const float*)d_in[0];
    const float* ctx  = (const float*)d_in[1];
    const float* l2sW = (const float*)d_in[2];
    const float* l2sb = (const float*)d_in[3];
    const float* sepW = (const float*)d_in[4];
    const float* sepb = (const float*)d_in[5];
    const float* aW   = (const float*)d_in[6];
    const float* ab   = (const float*)d_in[7];
    const float* Wx   = (const float*)d_in[8];
    const float* bx   = (const float*)d_in[9];
    const float* Wh   = (const float*)d_in[10];
    const float* bh   = (const float*)d_in[11];
    const float* Wc   = (const float*)d_in[12];
    const float* bc   = (const float*)d_in[13];
    float* out = (float*)d_out;

    k_share<<<dim3(128, 8), 256>>>(feat, l2sW, l2sb);
    k_groupsep<<<B * T, 128>>>(feat, sepW, sepb);
    for (int l = 0; l < LNUM; l++) {
        k_zero<<<256, 256>>>();
        for (int t = 0; t < T; t++) {
            k_prep<<<B * 2, 256>>>(ctx, aW, ab, l, t);
            k_gemm<<<dim3(40, 2, 4), 256>>>(Wx, Wh, Wc, l);
            k_finalize<<<B * 4, 128>>>(bx, bh, bc, l, t);
        }
    }
    k_output<<<(int)(((size_t)B * T * 1536 + 255) / 256), 256>>>(out);
}

// round 2
// speedup vs baseline: 1.3766x; 1.3766x over previous
#include <cuda_runtime.h>
#include <math.h>

#define B 64
#define T 128
#define M 4
#define D 512
#define H 512
#define LNUM 2
#define K 6
#define F5H 2560   // 5*H
#define KSPLIT 8   // one 512-wide weight chunk per split

// ---------------- persistent scratch (static device arrays; no allocation) ----
__device__ float g_bufA[(size_t)T * B * 2 * D];   // layer0 seq (group-sep) -> layer1 hid
__device__ float g_bufB[(size_t)T * B * 2 * D];   // layer0 hid -> layer1 seq
__device__ float g_shareA[(size_t)T * B * H];     // share_feat0 -> layer1 share out
__device__ float g_shareB[(size_t)T * B * H];     // layer0 share out
__device__ float g_Arow[(size_t)128 * 4096];      // rows r=j*64+b, masked concat input
__device__ float g_partial[(size_t)KSPLIT * 128 * F5H];
__device__ float g_cell[(size_t)B * 2 * H];
__device__ float g_shst[(size_t)B * H];
__device__ float g_cum[(size_t)B * H];
__device__ int   g_sel[B * 2 * 2];

// ---------------- share_feat = relu(feat_flat @ l2s_W + b) -------------------
__global__ __launch_bounds__(256) void k_share(const float* __restrict__ feat,
                                               const float* __restrict__ W,
                                               const float* __restrict__ bias) {
    __shared__ float As[16][64];
    __shared__ float Bs[16][64];
    int tid  = threadIdx.x;
    int row0 = blockIdx.x * 64;
    int col0 = blockIdx.y * 64;
    int tr = tid >> 4, tc = tid & 15;
    float acc[4][4];
#pragma unroll
    for (int i = 0; i < 4; i++)
#pragma unroll
        for (int jj = 0; jj < 4; jj++) acc[i][jj] = 0.f;

    for (int k0 = 0; k0 < M * D; k0 += 16) {
#pragma unroll
        for (int i = 0; i < 4; i++) {
            int idx = tid + i * 256;
            int r = idx >> 4, k = idx & 15;
            As[k][r] = feat[(size_t)(row0 + r) * (M * D) + k0 + k];
        }
#pragma unroll
        for (int i = 0; i < 4; i++) {
            int idx = tid + i * 256;
            int k = idx >> 6, c = idx & 63;
            Bs[k][c] = W[(size_t)(k0 + k) * H + col0 + c];
        }
        __syncthreads();
#pragma unroll
        for (int k = 0; k < 16; k++) {
            float4 a4 = *(const float4*)&As[k][tr * 4];
            float4 b4 = *(const float4*)&Bs[k][tc * 4];
            float av[4] = {a4.x, a4.y, a4.z, a4.w};
            float bv[4] = {b4.x, b4.y, b4.z, b4.w};
#pragma unroll
            for (int i = 0; i < 4; i++)
#pragma unroll
                for (int jj = 0; jj < 4; jj++) acc[i][jj] += av[i] * bv[jj];
        }
        __syncthreads();
    }
#pragma unroll
    for (int i = 0; i < 4; i++) {
        int row = row0 + tr * 4 + i;
        int bb = row >> 7, tt = row & 127;  // row = b*T + t
#pragma unroll
        for (int jj = 0; jj < 4; jj++) {
            int col = col0 + tc * 4 + jj;
            float v = acc[i][jj] + bias[col];
            g_shareA[((size_t)tt * B + bb) * H + col] = v > 0.f ? v : 0.f;
        }
    }
}

// ---------------- group separation -> g_bufA [t][b][j][d] --------------------
__global__ __launch_bounds__(128) void k_groupsep(const float* __restrict__ feat,
                                                  const float* __restrict__ sepW,
                                                  const float* __restrict__ sepb) {
    int bt = blockIdx.x;          // b*T + t
    int b = bt >> 7, t = bt & 127;
    const float* fb = feat + (size_t)bt * (M * D);
    __shared__ float s_lg[M];
    int tid = threadIdx.x;
    int w = tid >> 5, lane = tid & 31;
    if (w < M) {
        float s = 0.f;
        for (int d = lane; d < D; d += 32) s += fb[w * D + d] * sepW[d];
#pragma unroll
        for (int o = 16; o; o >>= 1) s += __shfl_down_sync(0xffffffffu, s, o);
        if (lane == 0) s_lg[w] = s + sepb[0];
    }
    __syncthreads();
    float lg[M], mx = -1e30f;
#pragma unroll
    for (int m = 0; m < M; m++) { lg[m] = s_lg[m]; mx = fmaxf(mx, lg[m]); }
    float e[M], sum = 0.f;
#pragma unroll
    for (int m = 0; m < M; m++) { e[m] = expf(lg[m] - mx); sum += e[m]; }
    float sw[M], cnt0 = 0.f;
#pragma unroll
    for (int m = 0; m < M; m++) { sw[m] = (e[m] > 0.25f * sum) ? 1.f : 0.f; cnt0 += sw[m]; }
    float cnt1 = (float)M - cnt0;
    float inv0 = 1.f / (cnt0 + 1e-8f), inv1 = 1.f / (cnt1 + 1e-8f);
    float* o0 = g_bufA + ((size_t)t * B + b) * 2 * D;
    float* o1 = o0 + D;
    for (int d = tid; d < D; d += 128) {
        float s0 = 0.f, s1 = 0.f;
#pragma unroll
        for (int m = 0; m < M; m++) {
            float v = fb[m * D + d];
            s0 += sw[m] * v;
            s1 += (1.f - sw[m]) * v;
        }
        o0[d] = s0 * inv0;
        o1[d] = s1 * inv1;
    }
}

// ---------------- fused: finalize(t-1) + prep(t); one block per b ------------
__global__ __launch_bounds__(512) void k_step(const float* __restrict__ ctx,
                                              const float* __restrict__ archW,
                                              const float* __restrict__ archb,
                                              const float* __restrict__ bxp,
                                              const float* __restrict__ bhp,
                                              const float* __restrict__ bcp,
                                              int l, int t) {
    int b = blockIdx.x;
    int tid = threadIdx.x;
    const float* seq = l ? g_bufB : g_bufA;
    float* hid = l ? g_bufA : g_bufB;
    const float* shin = l ? g_shareB : g_shareA;
    float* shout = l ? g_shareA : g_shareB;

    __shared__ float s_h1[2][D];
    __shared__ float s_lg[2][K];
    __shared__ int s_sel[4];

    if (t == 0) {
        for (int i = tid; i < 2 * H; i += 512) g_cell[(size_t)b * 2 * H + i] = 0.f;
        for (int i = tid; i < H; i += 512) { g_shst[(size_t)b * H + i] = 0.f; g_cum[(size_t)b * H + i] = 0.f; }
        s_h1[0][tid] = 0.f;
        s_h1[1][tid] = 0.f;
    } else {
        int tp = t - 1;
        int p = tid;  // 0..511
        float sgsum = 0.f;
#pragma unroll
        for (int j = 0; j < 2; j++) {
            int k0 = g_sel[(b * 2 + j) * 2], k1 = g_sel[(b * 2 + j) * 2 + 1];
            float tot[5];
#pragma unroll
            for (int c = 0; c < 5; c++) {
                int f = c * 512 + p;
                size_t base = (size_t)(j * 64 + b) * F5H + f;
                float v = 0.f;
#pragma unroll
                for (int ks = 0; ks < KSPLIT; ks++)
                    v += g_partial[(size_t)ks * 128 * F5H + base];
                v += bxp[(size_t)(l * 2 + j) * F5H + f] + bhp[(size_t)(l * 2 + j) * F5H + f];
                v += 0.5f * (bcp[((size_t)(l * 2 + j) * K + k0) * F5H + f]
                           + bcp[((size_t)(l * 2 + j) * K + k1) * F5H + f]);
                tot[c] = v;
            }
            float ig = tot[0], fg = tot[1], og = tot[2], sg = tot[3], cc = tot[4];
            size_t ci = ((size_t)b * 2 + j) * H + p;
            float cell = g_cell[ci];
            float sf = 1.f / (1.f + expf(-fg));
            float si = 1.f / (1.f + expf(-ig));
            cell = (1.f - sf) * cell + si * tanhf(cc);
            g_cell[ci] = cell;
            float hv = (1.f / (1.f + expf(-og))) * tanhf(cell);
            hid[((size_t)tp * B + b) * 2 * H + (size_t)j * H + p] = hv;
            s_h1[j][p] = hv;
            sgsum += sg;
        }
        float gate = 1.f / (1.f + expf(-sgsum));
        size_t si = (size_t)b * H + p;
        float shf = shin[((size_t)tp * B + b) * H + p];
        float st = g_shst[si] + gate * shf;
        float cum = g_cum[si] + gate;
        g_shst[si] = st;
        g_cum[si] = cum;
        shout[((size_t)tp * B + b) * H + p] = st / cum;
    }
    if (t >= T) return;
    __syncthreads();

    // logits: 12 warps do (j,k) dot products over D
    int w = tid >> 5, lane = tid & 31;
    if (w < 12) {
        int j = w / K, k = w % K;
        const float* aW = archW + (size_t)l * H * K;
        float s = 0.f;
        for (int d = lane; d < D; d += 32) s += s_h1[j][d] * aW[(size_t)d * K + k];
#pragma unroll
        for (int o = 16; o; o >>= 1) s += __shfl_down_sync(0xffffffffu, s, o);
        if (lane == 0) s_lg[j][k] = s + archb[l * K + k];
    }
    __syncthreads();
    if (tid < 2) {
        int j = tid;
        int k0 = 0; float best = s_lg[j][0];
        for (int k = 1; k < K; k++) if (s_lg[j][k] > best) { best = s_lg[j][k]; k0 = k; }
        int k1 = -1; float b2 = 0.f;
        for (int k = 0; k < K; k++) {
            if (k == k0) continue;
            if (k1 < 0 || s_lg[j][k] > b2) { b2 = s_lg[j][k]; k1 = k; }
        }
        s_sel[j * 2] = k0; s_sel[j * 2 + 1] = k1;
        g_sel[(b * 2 + j) * 2] = k0;
        g_sel[(b * 2 + j) * 2 + 1] = k1;
    }
    __syncthreads();

    const float* seq_t  = seq + ((size_t)t * B + b) * 2 * D;
    const float* seq_n  = (t + 1 < T) ? seq + ((size_t)(t + 1) * B + b) * 2 * D : 0;
    const float* h_prev2 = (t >= 2) ? hid + ((size_t)(t - 2) * B + b) * 2 * D : 0;
    const float* sc = ctx + ((size_t)b * T + t) * H;

    for (int idx = tid; idx < 2 * 4096; idx += 512) {
        int j = idx >> 12;
        int q = idx & 4095;
        int c = q >> 9;
        int d = q & 511;
        int k0 = s_sel[j * 2], k1 = s_sel[j * 2 + 1];
        float v;
        if (c == 0) v = seq_t[j * D + d];
        else if (c == 1) v = s_h1[j][d];
        else {
            int k = c - 2;
            float cv;
            if (k == 0)      cv = h_prev2 ? h_prev2[j * D + d] : 0.f;
            else if (k == 1) cv = seq_n ? seq_n[j * D + d] : 0.f;
            else if (k == 2) cv = s_h1[1 - j][d];
            else if (k == 3) cv = seq_t[(1 - j) * D + d];
            else if (k == 4) cv = seq_n ? seq_n[(1 - j) * D + d] : 0.f;
            else             cv = sc[d];
            v = (k == k0 || k == k1) ? 0.5f * cv : 0.f;
        }
        g_Arow[(size_t)(j * 64 + b) * 4096 + q] = v;
    }
}

// ---------------- per-step GEMM: partial[ks] = A[:,chunk ks] @ Wchunk --------
// block: 64 rows (one j) x 128 cols, K=512 (exactly one weight chunk)
__global__ __launch_bounds__(256) void k_gemm(const float* __restrict__ Wx,
                                              const float* __restrict__ Wh,
                                              const float* __restrict__ Wc,
                                              int l) {
    int col0 = blockIdx.x * 128;
    int j = blockIdx.y;
    int ks = blockIdx.z;   // chunk 0..7
    const float* Wb;
    if (ks == 0)      Wb = Wx + (size_t)(l * 2 + j) * D * F5H;
    else if (ks == 1) Wb = Wh + (size_t)(l * 2 + j) * H * F5H;
    else              Wb = Wc + ((size_t)(l * 2 + j) * K + (ks - 2)) * (size_t)D * F5H;

    __shared__ float As[2][16][64];
    __shared__ float Bs[2][16][128];
    int tid = threadIdx.x;
    int tr = tid >> 4, tc = tid & 15;

    const float* Abase = g_Arow + (size_t)(j * 64) * 4096 + (size_t)ks * 512;
    int la_r = tid >> 2, la_k = (tid & 3) * 4;
    int lb_k = tid >> 5, lb_c = (tid & 31) * 4;

    float acc[4][8];
#pragma unroll
    for (int i = 0; i < 4; i++)
#pragma unroll
        for (int c = 0; c < 8; c++) acc[i][c] = 0.f;

    float4 stA, stB0, stB1;
    stA  = *(const float4*)&Abase[(size_t)la_r * 4096 + la_k];
    stB0 = *(const float4*)&Wb[(size_t)lb_k * F5H + col0 + lb_c];
    stB1 = *(const float4*)&Wb[(size_t)(lb_k + 8) * F5H + col0 + lb_c];
    As[0][la_k + 0][la_r] = stA.x;
    As[0][la_k + 1][la_r] = stA.y;
    As[0][la_k + 2][la_r] = stA.z;
    As[0][la_k + 3][la_r] = stA.w;
    *(float4*)&Bs[0][lb_k][lb_c] = stB0;
    *(float4*)&Bs[0][lb_k + 8][lb_c] = stB1;
    __syncthreads();

#pragma unroll 1
    for (int it = 0; it < 32; ++it) {
        int cur = it & 1;
        if (it + 1 < 32) {
            int ko = (it + 1) * 16;
            stA  = *(const float4*)&Abase[(size_t)la_r * 4096 + ko + la_k];
            stB0 = *(const float4*)&Wb[(size_t)(ko + lb_k) * F5H + col0 + lb_c];
            stB1 = *(const float4*)&Wb[(size_t)(ko + lb_k + 8) * F5H + col0 + lb_c];
        }
#pragma unroll
        for (int k = 0; k < 16; ++k) {
            float4 a  = *(const float4*)&As[cur][k][tr * 4];
            float4 b0 = *(const float4*)&Bs[cur][k][tc * 8];
            float4 b1 = *(const float4*)&Bs[cur][k][tc * 8 + 4];
            float av[4] = {a.x, a.y, a.z, a.w};
            float bv[8] = {b0.x, b0.y, b0.z, b0.w, b1.x, b1.y, b1.z, b1.w};
#pragma unroll
            for (int i = 0; i < 4; i++)
#pragma unroll
                for (int c = 0; c < 8; c++) acc[i][c] += av[i] * bv[c];
        }
        if (it + 1 < 32) {
            int nb = cur ^ 1;
            As[nb][la_k + 0][la_r] = stA.x;
            As[nb][la_k + 1][la_r] = stA.y;
            As[nb][la_k + 2][la_r] = stA.z;
            As[nb][la_k + 3][la_r] = stA.w;
            *(float4*)&Bs[nb][lb_k][lb_c] = stB0;
            *(float4*)&Bs[nb][lb_k + 8][lb_c] = stB1;
            __syncthreads();
        }
    }

    float* out = g_partial + ((size_t)ks * 128 + j * 64) * F5H + col0;
#pragma unroll
    for (int i = 0; i < 4; i++) {
        int row = tr * 4 + i;
        float4 o0 = make_float4(acc[i][0], acc[i][1], acc[i][2], acc[i][3]);
        float4 o1 = make_float4(acc[i][4], acc[i][5], acc[i][6], acc[i][7]);
        *(float4*)&out[(size_t)row * F5H + tc * 8]     = o0;
        *(float4*)&out[(size_t)row * F5H + tc * 8 + 4] = o1;
    }
}

// ---------------- output assembly -------------------------------------------
__global__ void k_output(float* __restrict__ out) {
    size_t i = (size_t)blockIdx.x * 256 + threadIdx.x;
    size_t total = (size_t)B * T * 1536;
    if (i >= total) return;
    int c = (int)(i % 1536);
    size_t bt = i / 1536;           // b*T + t
    int b = (int)(bt >> 7), t = (int)(bt & 127);
    float v;
    if (c < 1024) {
        size_t idx = ((size_t)t * B + b) * 1024 + c;
        v = 0.5f * (g_bufB[idx] + g_bufA[idx]);
    } else {
        int p = c - 1024;
        size_t idx = ((size_t)t * B + b) * H + p;
        v = 0.5f * (g_shareB[idx] + g_shareA[idx]);
    }
    out[i] = v;
}

// ---------------- launch ------------------------------------------------------
extern "C" void kernel_launch(void* const* d_in, const int* in_sizes, int n_in,
                              void* d_out, int out_size) {
    const float* feat = (const float*)d_in[0];
    const float* ctx  = (const float*)d_in[1];
    const float* l2sW = (const float*)d_in[2];
    const float* l2sb = (const float*)d_in[3];
    const float* sepW = (const float*)d_in[4];
    const float* sepb = (const float*)d_in[5];
    const float* aW   = (const float*)d_in[6];
    const float* ab   = (const float*)d_in[7];
    const float* Wx   = (const float*)d_in[8];
    const float* bx   = (const float*)d_in[9];
    const float* Wh   = (const float*)d_in[10];
    const float* bh   = (const float*)d_in[11];
    const float* Wc   = (const float*)d_in[12];
    const float* bc   = (const float*)d_in[13];
    float* out = (float*)d_out;

    k_share<<<dim3(128, 8), 256>>>(feat, l2sW, l2sb);
    k_groupsep<<<B * T, 128>>>(feat, sepW, sepb);
    for (int l = 0; l < LNUM; l++) {
        for (int t = 0; t < T; t++) {
            k_step<<<B, 512>>>(ctx, aW, ab, bx, bh, bc, l, t);
            k_gemm<<<dim3(20, 2, KSPLIT), 256>>>(Wx, Wh, Wc, l);
        }
        k_step<<<B, 512>>>(ctx, aW, ab, bx, bh, bc, l, T);  // trailing finalize
    }
    k_output<<<(int)(((size_t)B * T * 1536 + 255) / 256), 256>>>(out);
}

// round 5
// speedup vs baseline: 3.0124x; 2.1882x over previous
#include <cuda_runtime.h>
#include <math.h>
#include <stdint.h>

#define B 64
#define T 128
#define M 4
#define D 512
#define H 512
#define LNUM 2
#define K 6
#define F5H 2560   // 5*H

#define AST 36     // A smem row stride (conflict-free for frag loads)
#define BST 136    // B smem row stride

// gemm: Ah/Al [2][32][AST] + Bh/Bl [2][32][BST]
#define SMEM_G ((2*32*AST*2 + 2*32*BST*2) * 4)
// share: Ah/Al [2][64][AST] + Bh/Bl [2][32][BST]
#define SMEM_S ((2*64*AST*2 + 2*32*BST*2) * 4)

// ---------------- persistent scratch ----------------------------------------
__device__ float g_bufA[(size_t)T * B * 2 * D];
__device__ float g_bufB[(size_t)T * B * 2 * D];
__device__ float g_shareA[(size_t)T * B * H];
__device__ float g_shareB[(size_t)T * B * H];
__device__ float g_Arow[(size_t)128 * 4096];      // rows r=j*64+b, raw fp32
__device__ float g_partial[(size_t)8 * 128 * F5H];
__device__ float g_cell[(size_t)B * 2 * H];
__device__ float g_shst[(size_t)B * H];
__device__ float g_cum[(size_t)B * H];
__device__ int   g_sel[B * 2 * 2];

__device__ __forceinline__ float to_tf32(float x) {
    float r; asm("cvt.rna.tf32.f32 %0, %1;" : "=f"(r) : "f"(x)); return r;
}
__device__ __forceinline__ void split2(float x, float& hi, float& lo) {
    hi = to_tf32(x);
    lo = to_tf32(x - hi);
}

__device__ __forceinline__ void mma8(float& c0, float& c1, float& c2, float& c3,
                                     uint32_t a0, uint32_t a1, uint32_t a2, uint32_t a3,
                                     uint32_t b0, uint32_t b1) {
    asm volatile("mma.sync.aligned.m16n8k8.row.col.f32.tf32.tf32.f32 "
                 "{%0,%1,%2,%3}, {%4,%5,%6,%7}, {%8,%9}, {%0,%1,%2,%3};"
                 : "+f"(c0), "+f"(c1), "+f"(c2), "+f"(c3)
                 : "r"(a0), "r"(a1), "r"(a2), "r"(a3), "r"(b0), "r"(b1));
}

// ---------------- 3xtf32 share GEMM: [8192,2048]@[2048,512]+bias+relu --------
__global__ __launch_bounds__(256) void k_share(const float* __restrict__ feat,
                                               const float* __restrict__ W,
                                               const float* __restrict__ bias) {
    int col0 = blockIdx.x * 128;
    int row0 = blockIdx.y * 64;
    const float* Abase = feat + (size_t)row0 * 2048;

    extern __shared__ float sm[];
    float* Ah = sm;
    float* Al = Ah + 2 * 64 * AST;
    float* Bh = Al + 2 * 64 * AST;
    float* Bl = Bh + 2 * 32 * BST;

    int tid = threadIdx.x;
    int warp = tid >> 5, lane = tid & 31;
    int wm = warp >> 2, wn = warp & 3;
    int tg = lane >> 2, tig = lane & 3;
    int ar = tid >> 3, ac = (tid & 7) * 4;
    int br = warp, bc = lane * 4;

    float acc[2][4][4];
#pragma unroll
    for (int a = 0; a < 2; a++)
#pragma unroll
        for (int b = 0; b < 4; b++)
#pragma unroll
            for (int c = 0; c < 4; c++) acc[a][b][c] = 0.f;

    // prologue: stage 0
    {
        float4 v0 = *(const float4*)&Abase[(size_t)ar * 2048 + ac];
        float4 v1 = *(const float4*)&Abase[(size_t)(ar + 32) * 2048 + ac];
        float h0, l0;
        float* pa = (float*)&v0;
#pragma unroll
        for (int q = 0; q < 4; q++) { split2(pa[q], h0, l0); Ah[(size_t)ar*AST + ac + q] = h0; Al[(size_t)ar*AST + ac + q] = l0; }
        pa = (float*)&v1;
#pragma unroll
        for (int q = 0; q < 4; q++) { split2(pa[q], h0, l0); Ah[(size_t)(ar+32)*AST + ac + q] = h0; Al[(size_t)(ar+32)*AST + ac + q] = l0; }
#pragma unroll
        for (int i = 0; i < 4; i++) {
            int kr = br + i * 8;
            float4 w = *(const float4*)&W[(size_t)kr * 512 + col0 + bc];
            float* pw = (float*)&w;
#pragma unroll
            for (int q = 0; q < 4; q++) { split2(pw[q], h0, l0); Bh[(size_t)kr*BST + bc + q] = h0; Bl[(size_t)kr*BST + bc + q] = l0; }
        }
    }
    __syncthreads();

    for (int kt = 0; kt < 64; kt++) {
        int cur = kt & 1;
        float4 pa0, pa1, pwv[4];
        if (kt < 63) {
            int k0 = (kt + 1) * 32;
            pa0 = *(const float4*)&Abase[(size_t)ar * 2048 + k0 + ac];
            pa1 = *(const float4*)&Abase[(size_t)(ar + 32) * 2048 + k0 + ac];
#pragma unroll
            for (int i = 0; i < 4; i++)
                pwv[i] = *(const float4*)&W[(size_t)(k0 + br + i * 8) * 512 + col0 + bc];
        }
        const float* Ach = Ah + cur * 64 * AST;
        const float* Acl = Al + cur * 64 * AST;
        const float* Bch = Bh + cur * 32 * BST;
        const float* Bcl = Bl + cur * 32 * BST;
#pragma unroll
        for (int k8 = 0; k8 < 4; k8++) {
            int kb = k8 * 8;
            uint32_t afh[2][4], afl[2][4];
#pragma unroll
            for (int mm = 0; mm < 2; mm++) {
                int r0 = wm * 32 + mm * 16;
                afh[mm][0] = __float_as_uint(Ach[(size_t)(r0 + tg) * AST + kb + tig]);
                afh[mm][1] = __float_as_uint(Ach[(size_t)(r0 + tg + 8) * AST + kb + tig]);
                afh[mm][2] = __float_as_uint(Ach[(size_t)(r0 + tg) * AST + kb + tig + 4]);
                afh[mm][3] = __float_as_uint(Ach[(size_t)(r0 + tg + 8) * AST + kb + tig + 4]);
                afl[mm][0] = __float_as_uint(Acl[(size_t)(r0 + tg) * AST + kb + tig]);
                afl[mm][1] = __float_as_uint(Acl[(size_t)(r0 + tg + 8) * AST + kb + tig]);
                afl[mm][2] = __float_as_uint(Acl[(size_t)(r0 + tg) * AST + kb + tig + 4]);
                afl[mm][3] = __float_as_uint(Acl[(size_t)(r0 + tg + 8) * AST + kb + tig + 4]);
            }
#pragma unroll
            for (int nn = 0; nn < 4; nn++) {
                int n = wn * 32 + nn * 8 + tg;
                uint32_t bh0 = __float_as_uint(Bch[(size_t)(kb + tig) * BST + n]);
                uint32_t bh1 = __float_as_uint(Bch[(size_t)(kb + tig + 4) * BST + n]);
                uint32_t bl0 = __float_as_uint(Bcl[(size_t)(kb + tig) * BST + n]);
                uint32_t bl1 = __float_as_uint(Bcl[(size_t)(kb + tig + 4) * BST + n]);
#pragma unroll
                for (int mm = 0; mm < 2; mm++) {
                    mma8(acc[mm][nn][0], acc[mm][nn][1], acc[mm][nn][2], acc[mm][nn][3],
                         afh[mm][0], afh[mm][1], afh[mm][2], afh[mm][3], bh0, bh1);
                    mma8(acc[mm][nn][0], acc[mm][nn][1], acc[mm][nn][2], acc[mm][nn][3],
                         afh[mm][0], afh[mm][1], afh[mm][2], afh[mm][3], bl0, bl1);
                    mma8(acc[mm][nn][0], acc[mm][nn][1], acc[mm][nn][2], acc[mm][nn][3],
                         afl[mm][0], afl[mm][1], afl[mm][2], afl[mm][3], bh0, bh1);
                }
            }
        }
        if (kt < 63) {
            int nb = cur ^ 1;
            float h0, l0;
            float* p = (float*)&pa0;
#pragma unroll
            for (int q = 0; q < 4; q++) { split2(p[q], h0, l0); Ah[((size_t)nb*64 + ar)*AST + ac + q] = h0; Al[((size_t)nb*64 + ar)*AST + ac + q] = l0; }
            p = (float*)&pa1;
#pragma unroll
            for (int q = 0; q < 4; q++) { split2(p[q], h0, l0); Ah[((size_t)nb*64 + ar + 32)*AST + ac + q] = h0; Al[((size_t)nb*64 + ar + 32)*AST + ac + q] = l0; }
#pragma unroll
            for (int i = 0; i < 4; i++) {
                p = (float*)&pwv[i];
                int kr = nb * 32 + br + i * 8;
#pragma unroll
                for (int q = 0; q < 4; q++) { split2(p[q], h0, l0); Bh[(size_t)kr*BST + bc + q] = h0; Bl[(size_t)kr*BST + bc + q] = l0; }
            }
            __syncthreads();
        }
    }

#pragma unroll
    for (int mm = 0; mm < 2; mm++)
#pragma unroll
        for (int nn = 0; nn < 4; nn++) {
            int r = row0 + wm * 32 + mm * 16 + tg;
            int c = col0 + wn * 32 + nn * 8 + tig * 2;
#pragma unroll
            for (int h = 0; h < 2; h++) {
                int rr = r + h * 8;
                int bb = rr >> 7, tt = rr & 127;
                float v0 = acc[mm][nn][h * 2 + 0] + bias[c];
                float v1 = acc[mm][nn][h * 2 + 1] + bias[c + 1];
                v0 = v0 > 0.f ? v0 : 0.f;
                v1 = v1 > 0.f ? v1 : 0.f;
                *(float2*)&g_shareA[((size_t)tt * B + bb) * H + c] = make_float2(v0, v1);
            }
        }
}

// ---------------- group separation -> g_bufA [t][b][j][d] --------------------
__global__ __launch_bounds__(128) void k_groupsep(const float* __restrict__ feat,
                                                  const float* __restrict__ sepW,
                                                  const float* __restrict__ sepb) {
    int bt = blockIdx.x;          // b*T + t
    int b = bt >> 7, t = bt & 127;
    const float* fb = feat + (size_t)bt * (M * D);
    __shared__ float s_lg[M];
    int tid = threadIdx.x;
    int w = tid >> 5, lane = tid & 31;
    if (w < M) {
        float s = 0.f;
        for (int d = lane; d < D; d += 32) s += fb[w * D + d] * sepW[d];
#pragma unroll
        for (int o = 16; o; o >>= 1) s += __shfl_down_sync(0xffffffffu, s, o);
        if (lane == 0) s_lg[w] = s + sepb[0];
    }
    __syncthreads();
    float lg[M], mx = -1e30f;
#pragma unroll
    for (int m = 0; m < M; m++) { lg[m] = s_lg[m]; mx = fmaxf(mx, lg[m]); }
    float e[M], sum = 0.f;
#pragma unroll
    for (int m = 0; m < M; m++) { e[m] = expf(lg[m] - mx); sum += e[m]; }
    float sw[M], cnt0 = 0.f;
#pragma unroll
    for (int m = 0; m < M; m++) { sw[m] = (e[m] > 0.25f * sum) ? 1.f : 0.f; cnt0 += sw[m]; }
    float cnt1 = (float)M - cnt0;
    float inv0 = 1.f / (cnt0 + 1e-8f), inv1 = 1.f / (cnt1 + 1e-8f);
    float* o0 = g_bufA + ((size_t)t * B + b) * 2 * D;
    float* o1 = o0 + D;
    for (int d = tid; d < D; d += 128) {
        float s0 = 0.f, s1 = 0.f;
#pragma unroll
        for (int m = 0; m < M; m++) {
            float v = fb[m * D + d];
            s0 += sw[m] * v;
            s1 += (1.f - sw[m]) * v;
        }
        o0[d] = s0 * inv0;
        o1[d] = s1 * inv1;
    }
}

// ---------------- fused: finalize(t-1) + prep(t); one block per b ------------
__global__ __launch_bounds__(512) void k_step(const float* __restrict__ ctx,
                                              const float* __restrict__ archW,
                                              const float* __restrict__ archb,
                                              const float* __restrict__ bxp,
                                              const float* __restrict__ bhp,
                                              const float* __restrict__ bcp,
                                              int l, int t) {
    int b = blockIdx.x;
    int tid = threadIdx.x;
    const float* seq = l ? g_bufB : g_bufA;
    float* hid = l ? g_bufA : g_bufB;
    const float* shin = l ? g_shareB : g_shareA;
    float* shout = l ? g_shareA : g_shareB;

    __shared__ float s_h1[2][D];
    __shared__ float s_lg[2][K];
    __shared__ int s_sel[4];

    if (t == 0) {
        for (int i = tid; i < 2 * H; i += 512) g_cell[(size_t)b * 2 * H + i] = 0.f;
        for (int i = tid; i < H; i += 512) { g_shst[(size_t)b * H + i] = 0.f; g_cum[(size_t)b * H + i] = 0.f; }
        s_h1[0][tid] = 0.f;
        s_h1[1][tid] = 0.f;
    } else {
        int tp = t - 1;
        int p = tid;
        float sgsum = 0.f;
#pragma unroll
        for (int j = 0; j < 2; j++) {
            int k0 = g_sel[(b * 2 + j) * 2], k1 = g_sel[(b * 2 + j) * 2 + 1];
            float tot[5];
#pragma unroll
            for (int c = 0; c < 5; c++) {
                int f = c * 512 + p;
                size_t base = (size_t)(j * 64 + b) * F5H + f;
                float v = g_partial[base]
                        + g_partial[(size_t)1 * 128 * F5H + base]
                        + 0.5f * (g_partial[(size_t)(2 + k0) * 128 * F5H + base]
                                + g_partial[(size_t)(2 + k1) * 128 * F5H + base]);
                v += bxp[(size_t)(l * 2 + j) * F5H + f] + bhp[(size_t)(l * 2 + j) * F5H + f];
                v += 0.5f * (bcp[((size_t)(l * 2 + j) * K + k0) * F5H + f]
                           + bcp[((size_t)(l * 2 + j) * K + k1) * F5H + f]);
                tot[c] = v;
            }
            float ig = tot[0], fg = tot[1], og = tot[2], sg = tot[3], cc = tot[4];
            size_t ci = ((size_t)b * 2 + j) * H + p;
            float cell = g_cell[ci];
            float sf = 1.f / (1.f + expf(-fg));
            float si = 1.f / (1.f + expf(-ig));
            cell = (1.f - sf) * cell + si * tanhf(cc);
            g_cell[ci] = cell;
            float hv = (1.f / (1.f + expf(-og))) * tanhf(cell);
            hid[((size_t)tp * B + b) * 2 * H + (size_t)j * H + p] = hv;
            s_h1[j][p] = hv;
            sgsum += sg;
        }
        float gate = 1.f / (1.f + expf(-sgsum));
        size_t si = (size_t)b * H + p;
        float shf = shin[((size_t)tp * B + b) * H + p];
        float st = g_shst[si] + gate * shf;
        float cum = g_cum[si] + gate;
        g_shst[si] = st;
        g_cum[si] = cum;
        shout[((size_t)tp * B + b) * H + p] = st / cum;
    }
    if (t >= T) return;
    __syncthreads();

    int w = tid >> 5, lane = tid & 31;
    if (w < 12) {
        int j = w / K, k = w % K;
        const float* aW = archW + (size_t)l * H * K;
        float s = 0.f;
        for (int d = lane; d < D; d += 32) s += s_h1[j][d] * aW[(size_t)d * K + k];
#pragma unroll
        for (int o = 16; o; o >>= 1) s += __shfl_down_sync(0xffffffffu, s, o);
        if (lane == 0) s_lg[j][k] = s + archb[l * K + k];
    }
    __syncthreads();
    if (tid < 2) {
        int j = tid;
        int k0 = 0; float best = s_lg[j][0];
        for (int k = 1; k < K; k++) if (s_lg[j][k] > best) { best = s_lg[j][k]; k0 = k; }
        int k1 = -1; float b2 = 0.f;
        for (int k = 0; k < K; k++) {
            if (k == k0) continue;
            if (k1 < 0 || s_lg[j][k] > b2) { b2 = s_lg[j][k]; k1 = k; }
        }
        s_sel[j * 2] = k0; s_sel[j * 2 + 1] = k1;
        g_sel[(b * 2 + j) * 2] = k0;
        g_sel[(b * 2 + j) * 2 + 1] = k1;
    }
    __syncthreads();

    const float* seq_t  = seq + ((size_t)t * B + b) * 2 * D;
    const float* seq_n  = (t + 1 < T) ? seq + ((size_t)(t + 1) * B + b) * 2 * D : 0;
    const float* h_prev2 = (t >= 2) ? hid + ((size_t)(t - 2) * B + b) * 2 * D : 0;
    const float* sc = ctx + ((size_t)b * T + t) * H;

    // unmasked concat row (raw fp32): chunks: 0=x_t, 1=h1, 2..7=candidates
    for (int idx = tid; idx < 2 * 4096; idx += 512) {
        int j = idx >> 12;
        int q = idx & 4095;
        int c = q >> 9;
        int d = q & 511;
        float v;
        if (c == 0) v = seq_t[j * D + d];
        else if (c == 1) v = s_h1[j][d];
        else {
            int k = c - 2;
            if (k == 0)      v = h_prev2 ? h_prev2[j * D + d] : 0.f;
            else if (k == 1) v = seq_n ? seq_n[j * D + d] : 0.f;
            else if (k == 2) v = s_h1[1 - j][d];
            else if (k == 3) v = seq_t[(1 - j) * D + d];
            else if (k == 4) v = seq_n ? seq_n[(1 - j) * D + d] : 0.f;
            else             v = sc[d];
        }
        g_Arow[(size_t)(j * 64 + b) * 4096 + q] = v;
    }
}

// ---------------- per-step 3xtf32 GEMM, M=32 tiles with candidate gather -----
// grid (20 cols, 2 j, 16 z): z<4: fixed chunks ks=z>>1 (x,h), tile=z&1
//                            z>=4: candidate k=(z-4)>>1, tile=(z-4)&1, gathered
__global__ __launch_bounds__(256) void k_gemm(const float* __restrict__ Wx,
                                              const float* __restrict__ Wh,
                                              const float* __restrict__ Wc,
                                              int l) {
    int col0 = blockIdx.x * 128;
    int j = blockIdx.y;
    int z = blockIdx.z;
    int tid = threadIdx.x;
    int warp = tid >> 5, lane = tid & 31;

    __shared__ int s_list[32];
    __shared__ int s_cnt;
    __shared__ unsigned s_mask[2];

    int ks, tile;
    if (z < 4) { ks = z >> 1; tile = z & 1; }
    else       { ks = 2 + ((z - 4) >> 1); tile = (z - 4) & 1; }

    if (z < 4) {
        if (tid < 32) s_list[tid] = tile * 32 + tid;
        if (tid == 0) s_cnt = 64;
    } else {
        int k = ks - 2;
        if (tid < 32) s_list[tid] = -1;
        if (warp < 2) {
            int b = warp * 32 + lane;
            int s0 = g_sel[(b * 2 + j) * 2];
            int s1 = g_sel[(b * 2 + j) * 2 + 1];
            bool f = (s0 == k) || (s1 == k);
            unsigned m = __ballot_sync(0xffffffffu, f);
            if (lane == 0) s_mask[warp] = m;
        }
        __syncthreads();
        unsigned m0 = s_mask[0], m1 = s_mask[1];
        if (tid == 0) s_cnt = __popc(m0) + __popc(m1);
        if (warp < 2) {
            unsigned m = warp ? m1 : m0;
            if ((m >> lane) & 1u) {
                int pos = (warp ? __popc(m0) : 0) + __popc(m & ((1u << lane) - 1u));
                int p = pos - tile * 32;
                if (p >= 0 && p < 32) s_list[p] = warp * 32 + lane;
            }
        }
    }
    __syncthreads();
    if (tile * 32 >= s_cnt) return;

    const float* Wb;
    if (ks == 0)      Wb = Wx + (size_t)(l * 2 + j) * D * F5H;
    else if (ks == 1) Wb = Wh + (size_t)(l * 2 + j) * H * F5H;
    else              Wb = Wc + ((size_t)(l * 2 + j) * K + (ks - 2)) * (size_t)D * F5H;
    int chunkoff = ks * 512;

    extern __shared__ float sm[];
    float* Ah = sm;
    float* Al = Ah + 2 * 32 * AST;
    float* Bh = Al + 2 * 32 * AST;
    float* Bl = Bh + 2 * 32 * BST;

    int wm = warp >> 2, wn = warp & 3;
    int tg = lane >> 2, tig = lane & 3;
    int ar = tid >> 3, ac = (tid & 7) * 4;
    int br = warp, bc = lane * 4;

    int arow = s_list[ar];
    const float* Ap = g_Arow + (size_t)(j * 64 + (arow >= 0 ? arow : 0)) * 4096 + chunkoff;

    float acc[4][4];
#pragma unroll
    for (int b = 0; b < 4; b++)
#pragma unroll
        for (int c = 0; c < 4; c++) acc[b][c] = 0.f;

    {
        float4 v = *(const float4*)&Ap[ac];
        float h0, l0;
        float* p = (float*)&v;
#pragma unroll
        for (int q = 0; q < 4; q++) { split2(p[q], h0, l0); Ah[(size_t)ar*AST + ac + q] = h0; Al[(size_t)ar*AST + ac + q] = l0; }
#pragma unroll
        for (int i = 0; i < 4; i++) {
            int kr = br + i * 8;
            float4 w = *(const float4*)&Wb[(size_t)kr * F5H + col0 + bc];
            float* pw = (float*)&w;
#pragma unroll
            for (int q = 0; q < 4; q++) { split2(pw[q], h0, l0); Bh[(size_t)kr*BST + bc + q] = h0; Bl[(size_t)kr*BST + bc + q] = l0; }
        }
    }
    __syncthreads();

    for (int kt = 0; kt < 16; kt++) {
        int cur = kt & 1;
        float4 pa, pwv[4];
        if (kt < 15) {
            int k0 = (kt + 1) * 32;
            pa = *(const float4*)&Ap[k0 + ac];
#pragma unroll
            for (int i = 0; i < 4; i++)
                pwv[i] = *(const float4*)&Wb[(size_t)(k0 + br + i * 8) * F5H + col0 + bc];
        }
        const float* Ach = Ah + cur * 32 * AST;
        const float* Acl = Al + cur * 32 * AST;
        const float* Bch = Bh + cur * 32 * BST;
        const float* Bcl = Bl + cur * 32 * BST;
#pragma unroll
        for (int k8 = 0; k8 < 4; k8++) {
            int kb = k8 * 8;
            int r0 = wm * 16;
            uint32_t afh[4], afl[4];
            afh[0] = __float_as_uint(Ach[(size_t)(r0 + tg) * AST + kb + tig]);
            afh[1] = __float_as_uint(Ach[(size_t)(r0 + tg + 8) * AST + kb + tig]);
            afh[2] = __float_as_uint(Ach[(size_t)(r0 + tg) * AST + kb + tig + 4]);
            afh[3] = __float_as_uint(Ach[(size_t)(r0 + tg + 8) * AST + kb + tig + 4]);
            afl[0] = __float_as_uint(Acl[(size_t)(r0 + tg) * AST + kb + tig]);
            afl[1] = __float_as_uint(Acl[(size_t)(r0 + tg + 8) * AST + kb + tig]);
            afl[2] = __float_as_uint(Acl[(size_t)(r0 + tg) * AST + kb + tig + 4]);
            afl[3] = __float_as_uint(Acl[(size_t)(r0 + tg + 8) * AST + kb + tig + 4]);
#pragma unroll
            for (int nn = 0; nn < 4; nn++) {
                int n = wn * 32 + nn * 8 + tg;
                uint32_t bh0 = __float_as_uint(Bch[(size_t)(kb + tig) * BST + n]);
                uint32_t bh1 = __float_as_uint(Bch[(size_t)(kb + tig + 4) * BST + n]);
                uint32_t bl0 = __float_as_uint(Bcl[(size_t)(kb + tig) * BST + n]);
                uint32_t bl1 = __float_as_uint(Bcl[(size_t)(kb + tig + 4) * BST + n]);
                mma8(acc[nn][0], acc[nn][1], acc[nn][2], acc[nn][3],
                     afh[0], afh[1], afh[2], afh[3], bh0, bh1);
                mma8(acc[nn][0], acc[nn][1], acc[nn][2], acc[nn][3],
                     afh[0], afh[1], afh[2], afh[3], bl0, bl1);
                mma8(acc[nn][0], acc[nn][1], acc[nn][2], acc[nn][3],
                     afl[0], afl[1], afl[2], afl[3], bh0, bh1);
            }
        }
        if (kt < 15) {
            int nb = cur ^ 1;
            float h0, l0;
            float* p = (float*)&pa;
#pragma unroll
            for (int q = 0; q < 4; q++) { split2(p[q], h0, l0); Ah[((size_t)nb*32 + ar)*AST + ac + q] = h0; Al[((size_t)nb*32 + ar)*AST + ac + q] = l0; }
#pragma unroll
            for (int i = 0; i < 4; i++) {
                p = (float*)&pwv[i];
                int kr = nb * 32 + br + i * 8;
#pragma unroll
                for (int q = 0; q < 4; q++) { split2(p[q], h0, l0); Bh[(size_t)kr*BST + bc + q] = h0; Bl[(size_t)kr*BST + bc + q] = l0; }
            }
            __syncthreads();
        }
    }

    float* outp = g_partial + (size_t)ks * 128 * F5H;
    int rlo = s_list[wm * 16 + tg];
    int rhi = s_list[wm * 16 + tg + 8];
#pragma unroll
    for (int nn = 0; nn < 4; nn++) {
        int c = col0 + wn * 32 + nn * 8 + tig * 2;
        if (rlo >= 0)
            *(float2*)&outp[(size_t)(j * 64 + rlo) * F5H + c] = make_float2(acc[nn][0], acc[nn][1]);
        if (rhi >= 0)
            *(float2*)&outp[(size_t)(j * 64 + rhi) * F5H + c] = make_float2(acc[nn][2], acc[nn][3]);
    }
}

// ---------------- output assembly -------------------------------------------
__global__ void k_output(float* __restrict__ out) {
    size_t i = (size_t)blockIdx.x * 256 + threadIdx.x;
    size_t total = (size_t)B * T * 1536;
    if (i >= total) return;
    int c = (int)(i % 1536);
    size_t bt = i / 1536;
    int b = (int)(bt >> 7), t = (int)(bt & 127);
    float v;
    if (c < 1024) {
        size_t idx = ((size_t)t * B + b) * 1024 + c;
        v = 0.5f * (g_bufB[idx] + g_bufA[idx]);
    } else {
        int p = c - 1024;
        size_t idx = ((size_t)t * B + b) * H + p;
        v = 0.5f * (g_shareB[idx] + g_shareA[idx]);
    }
    out[i] = v;
}

// ---------------- launch ------------------------------------------------------
extern "C" void kernel_launch(void* const* d_in, const int* in_sizes, int n_in,
                              void* d_out, int out_size) {
    const float* feat = (const float*)d_in[0];
    const float* ctx  = (const float*)d_in[1];
    const float* l2sW = (const float*)d_in[2];
    const float* l2sb = (const float*)d_in[3];
    const float* sepW = (const float*)d_in[4];
    const float* sepb = (const float*)d_in[5];
    const float* aW   = (const float*)d_in[6];
    const float* ab   = (const float*)d_in[7];
    const float* Wx   = (const float*)d_in[8];
    const float* bx   = (const float*)d_in[9];
    const float* Wh   = (const float*)d_in[10];
    const float* bh   = (const float*)d_in[11];
    const float* Wc   = (const float*)d_in[12];
    const float* bc   = (const float*)d_in[13];
    float* out = (float*)d_out;

    cudaFuncSetAttribute(k_gemm, cudaFuncAttributeMaxDynamicSharedMemorySize, SMEM_G);
    cudaFuncSetAttribute(k_share, cudaFuncAttributeMaxDynamicSharedMemorySize, SMEM_S);

    k_share<<<dim3(4, 128), 256, SMEM_S>>>(feat, l2sW, l2sb);
    k_groupsep<<<B * T, 128>>>(feat, sepW, sepb);
    for (int l = 0; l < LNUM; l++) {
        for (int t = 0; t < T; t++) {
            k_step<<<B, 512>>>(ctx, aW, ab, bx, bh, bc, l, t);
            k_gemm<<<dim3(20, 2, 16), 256, SMEM_G>>>(Wx, Wh, Wc, l);
        }
        k_step<<<B, 512>>>(ctx, aW, ab, bx, bh, bc, l, T);
    }
    k_output<<<(int)(((size_t)B * T * 1536 + 255) / 256), 256>>>(out);
}